// round 14
// baseline (speedup 1.0000x reference)
#include <cuda_runtime.h>
#include <cuda_bf16.h>
#include <cstdint>

#define NB  8
#define EHD 768
#define TD  512
#define PHD 320
#define UD  128
#define JHD 320
#define NC  34
#define WST 36            // w table stride [j][36]

typedef unsigned long long ull;

// Scratch (allocation-free rule: device globals)
__device__ float g_e[NB * TD * JHD];    // (B, T, JH)
__device__ float g_p[NB * UD * JHD];    // (B, U, JH)
__device__ float g_wt[JHD * WST];       // W_out transposed [j][c], padded

// ---------------- f32x2 helpers ----------------
static __device__ __forceinline__ ull pack2(float x, float y) {
    ull r;
    asm("mov.b64 %0, {%1, %2};" : "=l"(r) : "f"(x), "f"(y));
    return r;
}
static __device__ __forceinline__ void unpack2(ull v, float& x, float& y) {
    asm("mov.b64 {%0, %1}, %2;" : "=f"(x), "=f"(y) : "l"(v));
}
static __device__ __forceinline__ void ffma2(ull& acc, ull a, ull b) {
    asm("fma.rn.f32x2 %0, %1, %2, %0;" : "+l"(acc) : "l"(a), "l"(b));
}

// ---------------- projection GEMM v5: 64l x 64j x 16k, 8lx4j microtile ----------------
// out[b,l,j] = sum_h X[b,h,l] * W[j,h] + bias[j]
// Ws holds duplicated pairs: Ws[k][2j]=Ws[k][2j+1]=W[j][k].
#define XSTR 68    // 272B rows, 16B-aligned
#define WSTR 132   // 528B rows, 16B-aligned

__global__ __launch_bounds__(128) void proj_all_kernel(
    const float* __restrict__ enc, const float* __restrict__ W_enc,
    const float* __restrict__ b_enc,
    const float* __restrict__ dec, const float* __restrict__ W_pred,
    const float* __restrict__ b_pred,
    const float* __restrict__ W_out,
    float* __restrict__ e_out, float* __restrict__ p_out)
{
    // ---- prep branch: build transposed padded W_out table ----
    if (blockIdx.x == 10) {
        int base = (blockIdx.z * 5 + blockIdx.y) * 128 + threadIdx.x;  // 5120 threads
        for (int idx = base; idx < JHD * WST; idx += 5 * NB * 128) {
            int j = idx / WST, c = idx - j * WST;
            g_wt[idx] = (c < NC) ? W_out[c * JHD + j] : 0.f;
        }
        return;
    }

    __shared__ float Xs[2][16][XSTR];   // [k][l(64)]
    __shared__ float Ws[2][16][WSTR];   // [k][2j(128)] duplicated pairs

    const float* X; const float* W; const float* bias; float* out;
    int H, L, l0;
    if (blockIdx.x < 8) {
        X = enc; W = W_enc; bias = b_enc; out = e_out;
        H = EHD; L = TD; l0 = blockIdx.x * 64;
    } else {
        X = dec; W = W_pred; bias = b_pred; out = p_out;
        H = PHD; L = UD; l0 = (blockIdx.x - 8) * 64;
    }
    const int b  = blockIdx.z;
    const int j0 = blockIdx.y * 64;
    const int tid = threadIdx.x;
    const int tl = tid & 7;     // 8 l-groups x 8 l
    const int tj = tid >> 3;    // 16 j-groups x 4 j

    ull acc[4][4];              // [j-col m][l-pair p]
#pragma unroll
    for (int m = 0; m < 4; m++)
#pragma unroll
        for (int p = 0; p < 4; p++) acc[m][p] = 0ull;

    // loaders
    const int lrow = tid >> 3, lq = tid & 7;   // X: 16 k-rows x 8 thr, quads lq & lq+8
    const int jrow = tid >> 1, kq = tid & 1;   // W: 64 j-rows x 2 thr, quads kq & kq+2

    const float* Xg = X + ((size_t)b * H + lrow) * L + l0;
    const float* Wg = W + (size_t)(j0 + jrow) * H;
    const int NT = H / 16;

    float4 xr[2], wr[2];
    // prologue: tile 0
    xr[0] = *(const float4*)(Xg + lq * 4);
    xr[1] = *(const float4*)(Xg + lq * 4 + 32);
    wr[0] = *(const float4*)(Wg + kq * 4);
    wr[1] = *(const float4*)(Wg + (kq + 2) * 4);

#pragma unroll 1
    for (int tile = 0; tile < NT; tile++) {
        const int buf = tile & 1;
        // store X
        *(float4*)&Xs[buf][lrow][lq * 4] = xr[0];
        *(float4*)&Xs[buf][lrow][lq * 4 + 32] = xr[1];
        // store W duplicated (banks: 4*row + 2*jrow + parity*16 -> full coverage)
#pragma unroll
        for (int q2 = 0; q2 < 2; q2++) {
            const int q = kq + 2 * q2;
            *(float2*)&Ws[buf][q * 4 + 0][2 * jrow] =
                make_float2(q2 ? wr[1].x : wr[0].x, q2 ? wr[1].x : wr[0].x);
            *(float2*)&Ws[buf][q * 4 + 1][2 * jrow] =
                make_float2(q2 ? wr[1].y : wr[0].y, q2 ? wr[1].y : wr[0].y);
            *(float2*)&Ws[buf][q * 4 + 2][2 * jrow] =
                make_float2(q2 ? wr[1].z : wr[0].z, q2 ? wr[1].z : wr[0].z);
            *(float2*)&Ws[buf][q * 4 + 3][2 * jrow] =
                make_float2(q2 ? wr[1].w : wr[0].w, q2 ? wr[1].w : wr[0].w);
        }
        __syncthreads();
        // prefetch next tile
        if (tile + 1 < NT) {
            const int h0 = (tile + 1) * 16;
            xr[0] = *(const float4*)(Xg + (size_t)h0 * L + lq * 4);
            xr[1] = *(const float4*)(Xg + (size_t)h0 * L + lq * 4 + 32);
            wr[0] = *(const float4*)(Wg + h0 + kq * 4);
            wr[1] = *(const float4*)(Wg + h0 + (kq + 2) * 4);
        }
        // compute: per kk 4 LDS.128 + 16 FFMA2
#pragma unroll
        for (int kk = 0; kk < 16; kk++) {
            ulonglong2 ap0 = *(const ulonglong2*)&Xs[buf][kk][tl * 8];
            ulonglong2 ap1 = *(const ulonglong2*)&Xs[buf][kk][tl * 8 + 4];
            ulonglong2 wa = *(const ulonglong2*)&Ws[buf][kk][tj * 8];
            ulonglong2 wb = *(const ulonglong2*)&Ws[buf][kk][tj * 8 + 4];
            ffma2(acc[0][0], wa.x, ap0.x); ffma2(acc[0][1], wa.x, ap0.y);
            ffma2(acc[0][2], wa.x, ap1.x); ffma2(acc[0][3], wa.x, ap1.y);
            ffma2(acc[1][0], wa.y, ap0.x); ffma2(acc[1][1], wa.y, ap0.y);
            ffma2(acc[1][2], wa.y, ap1.x); ffma2(acc[1][3], wa.y, ap1.y);
            ffma2(acc[2][0], wb.x, ap0.x); ffma2(acc[2][1], wb.x, ap0.y);
            ffma2(acc[2][2], wb.x, ap1.x); ffma2(acc[2][3], wb.x, ap1.y);
            ffma2(acc[3][0], wb.y, ap0.x); ffma2(acc[3][1], wb.y, ap0.y);
            ffma2(acc[3][2], wb.y, ap1.x); ffma2(acc[3][3], wb.y, ap1.y);
        }
        if (tile + 1 < NT) __syncthreads();
    }

    float4 bi = *(const float4*)(bias + j0 + tj * 4);
#pragma unroll
    for (int p = 0; p < 4; p++) {
        float a0x, a0y, a1x, a1y, a2x, a2y, a3x, a3y;
        unpack2(acc[0][p], a0x, a0y);
        unpack2(acc[1][p], a1x, a1y);
        unpack2(acc[2][p], a2x, a2y);
        unpack2(acc[3][p], a3x, a3y);
        const int l = l0 + tl * 8 + 2 * p;
        float4 o0 = make_float4(a0x + bi.x, a1x + bi.y, a2x + bi.z, a3x + bi.w);
        float4 o1 = make_float4(a0y + bi.x, a1y + bi.y, a2y + bi.z, a3y + bi.w);
        *(float4*)(out + ((size_t)b * L + l    ) * JHD + j0 + tj * 4) = o0;
        *(float4*)(out + ((size_t)b * L + l + 1) * JHD + j0 + tj * 4) = o1;
    }
}

// ---------------- joint: EXACT R13 (258us, ~93% of rt=3 floor) ----------------
#define JS_E (16 * JHD)
#define JS_P (32 * JHD)
#define JS_W (WST * JHD)
#define JS_TOTAL ((JS_E + JS_P + JS_W) * 4)

__global__ __launch_bounds__(256, 2) void joint_kernel(
    const float* __restrict__ e, const float* __restrict__ p,
    const float* __restrict__ wt, const float* __restrict__ bo,
    float* __restrict__ out)
{
    extern __shared__ float sm[];
    float* e_s = sm;                     // [t][j] 16 x 320 (broadcast reads)
    float* p_s = sm + JS_E;              // [j][u ^ (j&31)]
    float* w_s = sm + JS_E + JS_P;       // [j][c] stride 36
    __shared__ float b_s[NC];

    const int tid  = threadIdx.x;
    const int wid  = tid >> 5;
    const int ul   = tid & 31;
    const int b    = blockIdx.z;
    const int tg   = blockIdx.y * 16;
    const int ublk = blockIdx.x;         // 0..3

    {
        const float* eb = e + ((size_t)b * TD + tg) * JHD;
        for (int idx = tid; idx < JS_E; idx += 256) e_s[idx] = eb[idx];
    }
    {
        const float* pb = p + ((size_t)b * UD + ublk * 32) * JHD;
        for (int idx = tid; idx < JS_P; idx += 256) {
            int u = idx / JHD, j = idx - u * JHD;
            p_s[j * 32 + (u ^ (j & 31))] = pb[idx];
        }
    }
    for (int idx = tid; idx < JS_W; idx += 256) w_s[idx] = wt[idx];
    if (tid < NC) b_s[tid] = bo[tid];
    __syncthreads();

    const float* e0p = e_s + (2 * wid) * JHD;
    const float* e1p = e0p + JHD;

    ull acc0[17], acc1[17];
#pragma unroll
    for (int q = 0; q < 17; q++) { acc0[q] = 0ull; acc1[q] = 0ull; }

#pragma unroll 2
    for (int j = 0; j < JHD; j++) {
        float pv = p_s[j * 32 + (ul ^ (j & 31))];
        float ev0 = e0p[j];
        float ev1 = e1p[j];
        float h0 = fmaxf(ev0 + pv, 0.f);
        float h1 = fmaxf(ev1 + pv, 0.f);
        ull h0p = pack2(h0, h0);
        ull h1p = pack2(h1, h1);
        const ulonglong2* wr = (const ulonglong2*)(w_s + j * WST);
#pragma unroll
        for (int q = 0; q < 8; q++) {
            ulonglong2 w = wr[q];
            ffma2(acc0[2 * q    ], h0p, w.x);
            ffma2(acc0[2 * q + 1], h0p, w.y);
            ffma2(acc1[2 * q    ], h1p, w.x);
            ffma2(acc1[2 * q + 1], h1p, w.y);
        }
        ull wl = ((const ull*)(w_s + j * WST))[16];
        ffma2(acc0[16], h0p, wl);
        ffma2(acc1[16], h1p, wl);
    }

    const int u = ublk * 32 + ul;
#pragma unroll 1
    for (int r = 0; r < 2; r++) {
        const ull* acc = r ? acc1 : acc0;
        float lg[NC];
        float mx = -3.402823466e38f;
#pragma unroll
        for (int q = 0; q < 17; q++) {
            float x, y;
            unpack2(acc[q], x, y);
            x += b_s[2 * q];
            y += b_s[2 * q + 1];
            lg[2 * q] = x;
            lg[2 * q + 1] = y;
            mx = fmaxf(mx, fmaxf(x, y));
        }
        float s = 0.f;
#pragma unroll
        for (int c = 0; c < NC; c++) s += __expf(lg[c] - mx);
        const float lse = mx + __logf(s);
        const int t = tg + 2 * wid + r;
        float* op = out + (((size_t)b * TD + t) * UD + u) * NC;
#pragma unroll
        for (int q = 0; q < 17; q++)
            *(float2*)(op + 2 * q) = make_float2(lg[2 * q] - lse, lg[2 * q + 1] - lse);
    }
}

// ---------------- launch ----------------
extern "C" void kernel_launch(void* const* d_in, const int* in_sizes, int n_in,
                              void* d_out, int out_size)
{
    const float* enc    = (const float*)d_in[0];
    const float* dec    = (const float*)d_in[1];
    const float* W_enc  = (const float*)d_in[2];
    const float* b_enc  = (const float*)d_in[3];
    const float* W_pred = (const float*)d_in[4];
    const float* b_pred = (const float*)d_in[5];
    const float* W_out  = (const float*)d_in[6];
    const float* b_out  = (const float*)d_in[7];
    float* out = (float*)d_out;

    float *e_buf = nullptr, *p_buf = nullptr, *wt = nullptr;
    cudaGetSymbolAddress((void**)&e_buf, g_e);
    cudaGetSymbolAddress((void**)&p_buf, g_p);
    cudaGetSymbolAddress((void**)&wt, g_wt);

    cudaFuncSetAttribute(joint_kernel,
                         cudaFuncAttributeMaxDynamicSharedMemorySize, JS_TOTAL);

    // x: 0..7 enc l-tiles (64 each), 8..9 dec l-tiles, 10 = prep_w branch
    proj_all_kernel<<<dim3(11, 5, NB), 128>>>(enc, W_enc, b_enc,
                                              dec, W_pred, b_pred, W_out,
                                              e_buf, p_buf);
    // 4 u-blocks x 32 t-blocks x 8 b = 1024 CTAs, 105KB smem, 2 CTAs/SM
    joint_kernel<<<dim3(UD / 32, TD / 16, NB), 256, JS_TOTAL>>>(
        e_buf, p_buf, wt, b_out, out);
}

// round 15
// speedup vs baseline: 1.0773x; 1.0773x over previous
#include <cuda_runtime.h>
#include <cuda_bf16.h>
#include <cstdint>

#define NB  8
#define EHD 768
#define TD  512
#define PHD 320
#define UD  128
#define JHD 320
#define NC  34
#define WST 36            // w table stride [j][36]

typedef unsigned long long ull;

// Scratch (allocation-free rule: device globals)
__device__ float g_e[NB * TD * JHD];    // (B, T, JH)
__device__ float g_p[NB * UD * JHD];    // (B, U, JH)
__device__ float g_wt[JHD * WST];       // W_out transposed [j][c], padded

// ---------------- f32x2 helpers ----------------
static __device__ __forceinline__ ull pack2(float x, float y) {
    ull r;
    asm("mov.b64 %0, {%1, %2};" : "=l"(r) : "f"(x), "f"(y));
    return r;
}
static __device__ __forceinline__ void unpack2(ull v, float& x, float& y) {
    asm("mov.b64 {%0, %1}, %2;" : "=f"(x), "=f"(y) : "l"(v));
}
static __device__ __forceinline__ void ffma2(ull& acc, ull a, ull b) {
    asm("fma.rn.f32x2 %0, %1, %2, %0;" : "+l"(acc) : "l"(a), "l"(b));
}

// ---------------- merged projection GEMM (R5 structure, empirically fastest) ----
// out[b,l,j] = sum_h X[b,h,l] * W[j,h] + bias[j]
// Tile 32 l x 64 j, 128 threads, 4x4 microtile, register double-buffered gmem.
// grid x: 0..15 enc l-tiles, 16..19 dec l-tiles, 20 = prep_w branch (concurrent).
__global__ __launch_bounds__(128) void proj_all_kernel(
    const float* __restrict__ enc, const float* __restrict__ W_enc,
    const float* __restrict__ b_enc,
    const float* __restrict__ dec, const float* __restrict__ W_pred,
    const float* __restrict__ b_pred,
    const float* __restrict__ W_out,
    float* __restrict__ e_out, float* __restrict__ p_out)
{
    if (blockIdx.x == 20) {
        int base = (blockIdx.z * 5 + blockIdx.y) * 128 + threadIdx.x;  // 5120 threads
        for (int idx = base; idx < JHD * WST; idx += 5 * NB * 128) {
            int j = idx / WST, c = idx - j * WST;
            g_wt[idx] = (c < NC) ? W_out[c * JHD + j] : 0.f;
        }
        return;
    }

    __shared__ float Xs[16][36];
    __shared__ float Ws[16][68];

    const float* X; const float* W; const float* bias; float* out;
    int H, L, l0;
    if (blockIdx.x < 16) {
        X = enc; W = W_enc; bias = b_enc; out = e_out;
        H = EHD; L = TD; l0 = blockIdx.x * 32;
    } else {
        X = dec; W = W_pred; bias = b_pred; out = p_out;
        H = PHD; L = UD; l0 = (blockIdx.x - 16) * 32;
    }
    const int b  = blockIdx.z;
    const int j0 = blockIdx.y * 64;
    const int tid = threadIdx.x;
    const int tl = tid & 7;
    const int tj = tid >> 3;

    ull acc[4][2];
#pragma unroll
    for (int m = 0; m < 4; m++) { acc[m][0] = 0ull; acc[m][1] = 0ull; }

    const int kkL = tid >> 3, vL = tid & 7;
    const int jjW = tid >> 1, hsel = (tid & 1) * 2;

    const float* Xg = X + ((size_t)b * H + kkL) * L + l0 + vL * 4;
    const float* Wg = W + (size_t)(j0 + jjW) * H;

    float4 xv = *(const float4*)(Xg);
    float4 wv0 = *(const float4*)(Wg + (hsel + 0) * 4);
    float4 wv1 = *(const float4*)(Wg + (hsel + 1) * 4);

    for (int h0 = 0; h0 < H; h0 += 16) {
        *(float4*)&Xs[kkL][vL * 4] = xv;
        Ws[(hsel + 0) * 4 + 0][jjW] = wv0.x;
        Ws[(hsel + 0) * 4 + 1][jjW] = wv0.y;
        Ws[(hsel + 0) * 4 + 2][jjW] = wv0.z;
        Ws[(hsel + 0) * 4 + 3][jjW] = wv0.w;
        Ws[(hsel + 1) * 4 + 0][jjW] = wv1.x;
        Ws[(hsel + 1) * 4 + 1][jjW] = wv1.y;
        Ws[(hsel + 1) * 4 + 2][jjW] = wv1.z;
        Ws[(hsel + 1) * 4 + 3][jjW] = wv1.w;
        __syncthreads();
        if (h0 + 16 < H) {
            xv  = *(const float4*)(Xg + (size_t)(h0 + 16) * L);
            wv0 = *(const float4*)(Wg + h0 + 16 + (hsel + 0) * 4);
            wv1 = *(const float4*)(Wg + h0 + 16 + (hsel + 1) * 4);
        }
#pragma unroll
        for (int kk = 0; kk < 16; kk++) {
            ulonglong2 ap = *(const ulonglong2*)&Xs[kk][tl * 4];
            float4 wq = *(const float4*)&Ws[kk][tj * 4];
            ull w0 = pack2(wq.x, wq.x);
            ull w1 = pack2(wq.y, wq.y);
            ull w2 = pack2(wq.z, wq.z);
            ull w3 = pack2(wq.w, wq.w);
            ffma2(acc[0][0], w0, ap.x); ffma2(acc[0][1], w0, ap.y);
            ffma2(acc[1][0], w1, ap.x); ffma2(acc[1][1], w1, ap.y);
            ffma2(acc[2][0], w2, ap.x); ffma2(acc[2][1], w2, ap.y);
            ffma2(acc[3][0], w3, ap.x); ffma2(acc[3][1], w3, ap.y);
        }
        __syncthreads();
    }

    float4 bi = *(const float4*)(bias + j0 + tj * 4);
#pragma unroll
    for (int pp = 0; pp < 2; pp++) {
        float a0x, a0y, a1x, a1y, a2x, a2y, a3x, a3y;
        unpack2(acc[0][pp], a0x, a0y);
        unpack2(acc[1][pp], a1x, a1y);
        unpack2(acc[2][pp], a2x, a2y);
        unpack2(acc[3][pp], a3x, a3y);
        const int l = l0 + tl * 4 + pp * 2;
        float4 o0 = make_float4(a0x + bi.x, a1x + bi.y, a2x + bi.z, a3x + bi.w);
        float4 o1 = make_float4(a0y + bi.x, a1y + bi.y, a2y + bi.z, a3y + bi.w);
        *(float4*)(out + ((size_t)b * L + l    ) * JHD + j0 + tj * 4) = o0;
        *(float4*)(out + ((size_t)b * L + l + 1) * JHD + j0 + tj * 4) = o1;
    }
}

// ---------------- joint: EXACT R13 (258us, ~93% of rt=3 floor) ----------------
#define JS_E (16 * JHD)
#define JS_P (32 * JHD)
#define JS_W (WST * JHD)
#define JS_TOTAL ((JS_E + JS_P + JS_W) * 4)

__global__ __launch_bounds__(256, 2) void joint_kernel(
    const float* __restrict__ e, const float* __restrict__ p,
    const float* __restrict__ wt, const float* __restrict__ bo,
    float* __restrict__ out)
{
    extern __shared__ float sm[];
    float* e_s = sm;                     // [t][j] 16 x 320 (broadcast reads)
    float* p_s = sm + JS_E;              // [j][u ^ (j&31)]
    float* w_s = sm + JS_E + JS_P;       // [j][c] stride 36
    __shared__ float b_s[NC];

    const int tid  = threadIdx.x;
    const int wid  = tid >> 5;
    const int ul   = tid & 31;
    const int b    = blockIdx.z;
    const int tg   = blockIdx.y * 16;
    const int ublk = blockIdx.x;         // 0..3

    {
        const float* eb = e + ((size_t)b * TD + tg) * JHD;
        for (int idx = tid; idx < JS_E; idx += 256) e_s[idx] = eb[idx];
    }
    {
        const float* pb = p + ((size_t)b * UD + ublk * 32) * JHD;
        for (int idx = tid; idx < JS_P; idx += 256) {
            int u = idx / JHD, j = idx - u * JHD;
            p_s[j * 32 + (u ^ (j & 31))] = pb[idx];
        }
    }
    for (int idx = tid; idx < JS_W; idx += 256) w_s[idx] = wt[idx];
    if (tid < NC) b_s[tid] = bo[tid];
    __syncthreads();

    const float* e0p = e_s + (2 * wid) * JHD;
    const float* e1p = e0p + JHD;

    ull acc0[17], acc1[17];
#pragma unroll
    for (int q = 0; q < 17; q++) { acc0[q] = 0ull; acc1[q] = 0ull; }

#pragma unroll 2
    for (int j = 0; j < JHD; j++) {
        float pv = p_s[j * 32 + (ul ^ (j & 31))];
        float ev0 = e0p[j];
        float ev1 = e1p[j];
        float h0 = fmaxf(ev0 + pv, 0.f);
        float h1 = fmaxf(ev1 + pv, 0.f);
        ull h0p = pack2(h0, h0);
        ull h1p = pack2(h1, h1);
        const ulonglong2* wr = (const ulonglong2*)(w_s + j * WST);
#pragma unroll
        for (int q = 0; q < 8; q++) {
            ulonglong2 w = wr[q];
            ffma2(acc0[2 * q    ], h0p, w.x);
            ffma2(acc0[2 * q + 1], h0p, w.y);
            ffma2(acc1[2 * q    ], h1p, w.x);
            ffma2(acc1[2 * q + 1], h1p, w.y);
        }
        ull wl = ((const ull*)(w_s + j * WST))[16];
        ffma2(acc0[16], h0p, wl);
        ffma2(acc1[16], h1p, wl);
    }

    const int u = ublk * 32 + ul;
#pragma unroll 1
    for (int r = 0; r < 2; r++) {
        const ull* acc = r ? acc1 : acc0;
        float lg[NC];
        float mx = -3.402823466e38f;
#pragma unroll
        for (int q = 0; q < 17; q++) {
            float x, y;
            unpack2(acc[q], x, y);
            x += b_s[2 * q];
            y += b_s[2 * q + 1];
            lg[2 * q] = x;
            lg[2 * q + 1] = y;
            mx = fmaxf(mx, fmaxf(x, y));
        }
        float s = 0.f;
#pragma unroll
        for (int c = 0; c < NC; c++) s += __expf(lg[c] - mx);
        const float lse = mx + __logf(s);
        const int t = tg + 2 * wid + r;
        float* op = out + (((size_t)b * TD + t) * UD + u) * NC;
#pragma unroll
        for (int q = 0; q < 17; q++)
            *(float2*)(op + 2 * q) = make_float2(lg[2 * q] - lse, lg[2 * q + 1] - lse);
    }
}

// ---------------- launch ----------------
extern "C" void kernel_launch(void* const* d_in, const int* in_sizes, int n_in,
                              void* d_out, int out_size)
{
    const float* enc    = (const float*)d_in[0];
    const float* dec    = (const float*)d_in[1];
    const float* W_enc  = (const float*)d_in[2];
    const float* b_enc  = (const float*)d_in[3];
    const float* W_pred = (const float*)d_in[4];
    const float* b_pred = (const float*)d_in[5];
    const float* W_out  = (const float*)d_in[6];
    const float* b_out  = (const float*)d_in[7];
    float* out = (float*)d_out;

    float *e_buf = nullptr, *p_buf = nullptr, *wt = nullptr;
    cudaGetSymbolAddress((void**)&e_buf, g_e);
    cudaGetSymbolAddress((void**)&p_buf, g_p);
    cudaGetSymbolAddress((void**)&wt, g_wt);

    cudaFuncSetAttribute(joint_kernel,
                         cudaFuncAttributeMaxDynamicSharedMemorySize, JS_TOTAL);

    // x: 0..15 enc l-tiles, 16..19 dec l-tiles, 20 = prep_w branch (concurrent)
    proj_all_kernel<<<dim3(21, 5, NB), 128>>>(enc, W_enc, b_enc,
                                              dec, W_pred, b_pred, W_out,
                                              e_buf, p_buf);
    // 4 u-blocks x 32 t-blocks x 8 b = 1024 CTAs, 105KB smem, 2 CTAs/SM
    joint_kernel<<<dim3(UD / 32, TD / 16, NB), 256, JS_TOTAL>>>(
        e_buf, p_buf, wt, b_out, out);
}